// round 14
// baseline (speedup 1.0000x reference)
#include <cuda_runtime.h>
#include <cuda_bf16.h>
#include <cstdint>

// ============================================================================
// HospitalStaffingModel, hybrid-precision warp MMA on sm_103.
// Round 14: L0 + Final GEMMs in bf16 (m16n8k16), L1 + Heads GEMMs in e4m3
// (m16n8k32) — fp8 only where L1TEX bytes concentrate (h1, h2 operands and
// W1/heads weights). Shell: 64 rows/CTA, 256 thr (8 N-warps, MT=4), 2 CTA/SM,
// pair-interleaved LDG.128 B images. Epilogues fp32-exact; masks from fp32 x.
// ============================================================================

typedef unsigned long long ull;
#define B_TOTAL 131072
#define EPSV    1e-5f
#define NEGV    -1e9f

// ---- prepacked weight fragment buffer (ull entries, pair-interleaved) -------
#define GW0 0u        // bf16 W0: 4 ks16 x 32 np -> 8192 ull
#define GW1 8192u     // fp8  W1: 16 ks32 x 16 np -> 16384
#define GWH 24576u    // fp8  [nW1|dW1]: 8 ks32 x 8 np -> 4096
#define GWF 28672u    // bf16 blockdiag(nW2,dW2): 4 ks16 x 16 np -> 4096
#define GTOT 32768u

__device__ __align__(1024) ull g_wfrag[GTOT];

// ---- SMEM layout (byte offsets) ---------------------------------------------
#define SO_CS    0        // 1920 f32 consts (7680 B)
#define SO_SN    7680     // 64 int
#define SO_SD    7936     // 64 int
#define SO_XH    8192     // xs bf16 [64][36]u32 (9216B, L0) / h2 e4m3 [64][272B]
#define SO_H1    25600    // h1 e4m3 [64][528B] (33792B); a3 bf16 [64][68]u32 after L1
#define SMEM_BYTES 59392

// ---- helpers -----------------------------------------------------------------
__device__ __forceinline__ uint32_t smem_u32(const void* p) {
    uint32_t a;
    asm("{ .reg .u64 t; cvta.to.shared.u64 t, %1; cvt.u32.u64 %0, t; }" : "=r"(a) : "l"(p));
    return a;
}
__device__ __forceinline__ uint32_t pack_bf16x2(float lo, float hi) {
    uint32_t r;
    asm("cvt.rn.bf16x2.f32 %0, %1, %2;" : "=r"(r) : "f"(hi), "f"(lo));
    return r;
}
__device__ __forceinline__ unsigned short pack_e4m3x2(float lo, float hi) {
    unsigned short r;
    asm("cvt.rn.satfinite.e4m3x2.f32 %0, %1, %2;" : "=h"(r) : "f"(hi), "f"(lo));
    return r;
}
__device__ __forceinline__ uint32_t pack4_e4m3(float f0, float f1, float f2, float f3) {
    const uint32_t lo = pack_e4m3x2(f0, f1);
    const uint32_t hi = pack_e4m3x2(f2, f3);
    return lo | (hi << 16);
}
__device__ __forceinline__ void mma16816(float* c, const uint32_t* a, uint32_t b0, uint32_t b1) {
    asm volatile(
        "mma.sync.aligned.m16n8k16.row.col.f32.bf16.bf16.f32 "
        "{%0,%1,%2,%3}, {%4,%5,%6,%7}, {%8,%9}, {%0,%1,%2,%3};"
        : "+f"(c[0]), "+f"(c[1]), "+f"(c[2]), "+f"(c[3])
        : "r"(a[0]), "r"(a[1]), "r"(a[2]), "r"(a[3]), "r"(b0), "r"(b1));
}
__device__ __forceinline__ void mma16832(float* c, const uint32_t* a, uint32_t b0, uint32_t b1) {
    asm volatile(
        "mma.sync.aligned.m16n8k32.row.col.f32.e4m3.e4m3.f32 "
        "{%0,%1,%2,%3}, {%4,%5,%6,%7}, {%8,%9}, {%0,%1,%2,%3};"
        : "+f"(c[0]), "+f"(c[1]), "+f"(c[2]), "+f"(c[3])
        : "r"(a[0]), "r"(a[1]), "r"(a[2]), "r"(a[3]), "r"(b0), "r"(b1));
}
__device__ __forceinline__ void ldsm_x4(uint32_t* r, uint32_t saddr) {
    asm volatile("ldmatrix.sync.aligned.m8n8.x4.shared.b16 {%0,%1,%2,%3}, [%4];"
                 : "=r"(r[0]), "=r"(r[1]), "=r"(r[2]), "=r"(r[3]) : "r"(saddr));
}

// ---- bf16 register-tiled block (u32 element strides), validated R10/R11 ------
template<int KS, int NT, int MT>
__device__ __forceinline__ void gemm_bf16(
    uint32_t act_saddr, int SA, int kpb,
    const uint4* __restrict__ wf, int NPW, int npb,
    int lane, float* C)
{
    constexpr int NP = NT / 2;
    constexpr int PF = (KS < 3) ? KS : 3;
    const int quad  = lane >> 3;
    const int lrow  = (quad & 1) * 8 + (lane & 7);
    const int khalf = quad >> 1;
    const uint4* __restrict__ wfl = wf + (size_t)npb * 32 + lane;

    uint32_t abase[MT];
    #pragma unroll
    for (int mt = 0; mt < MT; mt++)
        abase[mt] = act_saddr + (uint32_t)(((mt * 16 + lrow) * SA + kpb + khalf * 4) * 4);

    uint4 b[PF][NP];
    #pragma unroll
    for (int s = 0; s < PF - 1; s++)
        #pragma unroll
        for (int np = 0; np < NP; np++)
            b[s][np] = wfl[((size_t)s * NPW + np) * 32];

    uint32_t a[2][4];
    ldsm_x4(a[0], abase[0]);

    #pragma unroll
    for (int ks = 0; ks < KS; ks++) {
        if (ks + PF - 1 < KS) {
            #pragma unroll
            for (int np = 0; np < NP; np++)
                b[(ks + PF - 1) % PF][np] = wfl[((size_t)(ks + PF - 1) * NPW + np) * 32];
        }
        #pragma unroll
        for (int mt = 0; mt < MT; mt++) {
            const int cur = (ks * MT + mt) & 1;
            if (mt + 1 < MT)
                ldsm_x4(a[cur ^ 1], abase[mt + 1] + ks * 32);
            else if (ks + 1 < KS)
                ldsm_x4(a[cur ^ 1], abase[0] + (ks + 1) * 32);
            const uint4* bb = b[ks % PF];
            #pragma unroll
            for (int np = 0; np < NP; np++) {
                mma16816(C + (mt * NT + np * 2) * 4,     a[cur], bb[np].x, bb[np].y);
                mma16816(C + (mt * NT + np * 2 + 1) * 4, a[cur], bb[np].z, bb[np].w);
            }
        }
    }
}

// ---- fp8 register-tiled block (BYTE strides), validated R13 ------------------
template<int KS, int NT, int MT>
__device__ __forceinline__ void gemm_fp8(
    uint32_t act_b, int SAB, int kpb,
    const uint4* __restrict__ wf, int NPW, int npb,
    int lane, float* C)
{
    constexpr int NP = NT / 2;
    constexpr int PF = (KS < 3) ? KS : 3;
    const int quad  = lane >> 3;
    const int lrow  = (quad & 1) * 8 + (lane & 7);
    const int khalf = quad >> 1;
    const uint4* __restrict__ wfl = wf + (size_t)npb * 32 + lane;

    uint32_t abase[MT];
    #pragma unroll
    for (int mt = 0; mt < MT; mt++)
        abase[mt] = act_b + (uint32_t)((mt * 16 + lrow) * SAB + kpb + khalf * 16);

    uint4 b[PF][NP];
    #pragma unroll
    for (int s = 0; s < PF - 1; s++)
        #pragma unroll
        for (int np = 0; np < NP; np++)
            b[s][np] = wfl[((size_t)s * NPW + np) * 32];

    uint32_t a[2][4];
    ldsm_x4(a[0], abase[0]);

    #pragma unroll
    for (int ks = 0; ks < KS; ks++) {
        if (ks + PF - 1 < KS) {
            #pragma unroll
            for (int np = 0; np < NP; np++)
                b[(ks + PF - 1) % PF][np] = wfl[((size_t)(ks + PF - 1) * NPW + np) * 32];
        }
        #pragma unroll
        for (int mt = 0; mt < MT; mt++) {
            const int cur = (ks * MT + mt) & 1;
            if (mt + 1 < MT)
                ldsm_x4(a[cur ^ 1], abase[mt + 1] + ks * 32);
            else if (ks + 1 < KS)
                ldsm_x4(a[cur ^ 1], abase[0] + (ks + 1) * 32);
            const uint4* bb = b[ks % PF];
            #pragma unroll
            for (int np = 0; np < NP; np++) {
                mma16832(C + (mt * NT + np * 2) * 4,     a[cur], bb[np].x, bb[np].y);
                mma16832(C + (mt * NT + np * 2 + 1) * 4, a[cur], bb[np].z, bb[np].w);
            }
        }
    }
}

// ============================================================================
// Prepack: bf16 images for W0/final (R11 layout), fp8 images for W1/heads (R13).
// ============================================================================
__global__ void hosp_prepack(const float* __restrict__ W0, const float* __restrict__ W1,
                             const float* __restrict__ nW1, const float* __restrict__ dW1,
                             const float* __restrict__ nW2, const float* __restrict__ dW2)
{
    const int idx = blockIdx.x * 256 + threadIdx.x;
    if (idx >= (int)GTOT) return;
    const int lane32 = idx & 31;
    const int tg = lane32 & 3, gg = lane32 >> 2;

    if (idx < 8192) {                        // bf16 W0 [64K x 512N], NPW=32
        const int gidx = idx >> 5;
        const int ks = gidx >> 6, nt = gidx & 63;
        const int k0 = ks * 16 + tg * 2, n = nt * 8 + gg;
        const uint32_t r0 = pack_bf16x2(W0[(k0    ) * 512 + n], W0[(k0 + 1) * 512 + n]);
        const uint32_t r1 = pack_bf16x2(W0[(k0 + 8) * 512 + n], W0[(k0 + 9) * 512 + n]);
        g_wfrag[GW0 + ((size_t)(ks * 32 + (nt >> 1)) * 32 + lane32) * 2 + (nt & 1)]
            = (ull)r0 | ((ull)r1 << 32);
    } else if (idx < 24576) {                // fp8 W1 [512K x 256N], NPW=16
        const int e = idx - 8192;
        const int half = e & 1, e2 = e >> 1;
        const int lane = e2 & 31, gi = e2 >> 5;
        const int np = gi % 16, ks = gi / 16;
        const int nt = np * 2 + half;
        const int ltg = lane & 3, lgg = lane >> 2;
        const int k0 = ks * 32 + ltg * 4, n = nt * 8 + lgg;
        float f[8];
        #pragma unroll
        for (int i = 0; i < 4; i++) {
            f[i]     = W1[(size_t)(k0 + i)      * 256 + n];
            f[4 + i] = W1[(size_t)(k0 + 16 + i) * 256 + n];
        }
        const uint32_t b0 = pack4_e4m3(f[0], f[1], f[2], f[3]);
        const uint32_t b1 = pack4_e4m3(f[4], f[5], f[6], f[7]);
        g_wfrag[idx] = (ull)b0 | ((ull)b1 << 32);
    } else if (idx < 28672) {                // fp8 [nW1|dW1] [256K x 128N], NPW=8
        const int e = idx - 24576;
        const int half = e & 1, e2 = e >> 1;
        const int lane = e2 & 31, gi = e2 >> 5;
        const int np = gi % 8, ks = gi / 8;
        const int nt = np * 2 + half;
        const int ltg = lane & 3, lgg = lane >> 2;
        const int k0 = ks * 32 + ltg * 4;
        const int ng = nt * 8 + lgg;
        const float* W = (ng < 64) ? nW1 : dW1;
        const int n = ng & 63;
        float f[8];
        #pragma unroll
        for (int i = 0; i < 4; i++) {
            f[i]     = W[(size_t)(k0 + i)      * 64 + n];
            f[4 + i] = W[(size_t)(k0 + 16 + i) * 64 + n];
        }
        const uint32_t b0 = pack4_e4m3(f[0], f[1], f[2], f[3]);
        const uint32_t b1 = pack4_e4m3(f[4], f[5], f[6], f[7]);
        g_wfrag[idx] = (ull)b0 | ((ull)b1 << 32);
    } else {                                 // bf16 blockdiag(nW2,dW2), NPW=16
        const int gidx = (idx - 28672) >> 5;
        const int ks = gidx >> 5, nt = gidx & 31;
        const int k0 = ks * 16 + tg * 2;
        const float* W = (nt < 16) ? nW2 : dW2;
        const int n = ((nt & 15) * 8 + gg);
        const uint32_t r0 = pack_bf16x2(W[(k0    ) * 128 + n], W[(k0 + 1) * 128 + n]);
        const uint32_t r1 = pack_bf16x2(W[(k0 + 8) * 128 + n], W[(k0 + 9) * 128 + n]);
        g_wfrag[GWF + ((size_t)(ks * 16 + (nt >> 1)) * 32 + lane32) * 2 + (nt & 1)]
            = (ull)r0 | ((ull)r1 << 32);
    }
}

// ============================================================================
// Main kernel: 64 rows/CTA, 256 threads (8 N-warps, MT=4). 2 CTAs/SM. Hybrid.
// ============================================================================
__global__ __launch_bounds__(256, 2)
void hosp_hyb_kernel(
    const float* __restrict__ x,
    const float* __restrict__ b0,  const float* __restrict__ g0,
    const float* __restrict__ be0, const float* __restrict__ rm0, const float* __restrict__ rv0,
    const float* __restrict__ b1,  const float* __restrict__ g1,
    const float* __restrict__ be1, const float* __restrict__ rm1, const float* __restrict__ rv1,
    const float* __restrict__ nb1, const float* __restrict__ nb2,
    const float* __restrict__ db1, const float* __restrict__ db2,
    float* __restrict__ out)
{
    extern __shared__ unsigned char smem[];
    float* cs  = reinterpret_cast<float*>(smem + SO_CS);
    int*   sns = reinterpret_cast<int*>(smem + SO_SN);
    int*   sds = reinterpret_cast<int*>(smem + SO_SD);
    uint32_t* xs = reinterpret_cast<uint32_t*>(smem + SO_XH);   // bf16 x (L0 only)
    unsigned char* xh_p = smem + SO_XH;                         // h2 e4m3 after L0
    unsigned char* h1_p = smem + SO_H1;                         // h1 e4m3
    uint32_t* a3 = reinterpret_cast<uint32_t*>(smem + SO_H1);   // bf16 a3 after L1

    const uint32_t xh_b = smem_u32(smem + SO_XH);
    const uint32_t h1_b = smem_u32(smem + SO_H1);
    const uint4* wf4 = reinterpret_cast<const uint4*>(g_wfrag);

    const int tid  = threadIdx.x;
    const int lane = tid & 31;
    const int nw   = tid >> 5;         // N-warp (0..7)
    const int g    = lane >> 2, t = lane & 3;
    const int r0   = blockIdx.x * 64;

    // ---- fold BN consts + biases --------------------------------------------
    for (int i = tid; i < 512; i += 256) {
        const float s = g0[i] * rsqrtf(rv0[i] + EPSV);
        cs[i] = s; cs[512 + i] = (b0[i] - rm0[i]) * s + be0[i];
    }
    {
        const int i = tid;
        const float s = g1[i] * rsqrtf(rv1[i] + EPSV);
        cs[1024 + i] = s; cs[1280 + i] = (b1[i] - rm1[i]) * s + be1[i];
    }
    if (tid < 64) { cs[1536 + tid] = nb1[tid]; cs[1600 + tid] = db1[tid]; }
    if (tid < 128) { cs[1664 + tid] = nb2[tid]; cs[1792 + tid] = db2[tid]; }

    // ---- x tile: fp32 -> bf16x2, [64][36]u32 + mask thresholds ---------------
    {
        const float2* x2 = reinterpret_cast<const float2*>(x + (size_t)r0 * 64);
        for (int i = tid; i < 2048; i += 256) {
            const int row = i >> 5, kp = i & 31;
            const float2 v = x2[row * 32 + kp];
            xs[row * 36 + kp] = pack_bf16x2(v.x, v.y);
        }
        if (tid < 64)       sns[tid] = (int)x[(size_t)(r0 + tid) * 64 + 60];
        else if (tid < 128) sds[tid - 64] = (int)x[(size_t)(r0 + tid - 64) * 64 + 61];
    }
    __syncthreads();

    // ================= L0 (bf16): two N-halves; epilogue -> h1 e4m3 ===========
    #pragma unroll 1
    for (int half = 0; half < 2; half++) {
        float C[64];
        #pragma unroll
        for (int i = 0; i < 64; i++) C[i] = 0.0f;
        const int ntb = nw * 8 + half * 4;
        gemm_bf16<4, 4, 4>(xh_b, 36, 0, wf4 + (GW0 >> 1), 32, ntb >> 1, lane, C);
        #pragma unroll
        for (int mt = 0; mt < 4; mt++)
            #pragma unroll
            for (int nt = 0; nt < 4; nt++) {
                const float* c = C + (mt * 4 + nt) * 4;
                const int j = (ntb + nt) * 8 + t * 2;
                const int rA = mt * 16 + g, rB = rA + 8;
                const float v0 = fmaxf(fmaf(c[0], cs[j],     cs[512 + j]),     0.0f);
                const float v1 = fmaxf(fmaf(c[1], cs[j + 1], cs[512 + j + 1]), 0.0f);
                const float v2 = fmaxf(fmaf(c[2], cs[j],     cs[512 + j]),     0.0f);
                const float v3 = fmaxf(fmaf(c[3], cs[j + 1], cs[512 + j + 1]), 0.0f);
                *reinterpret_cast<unsigned short*>(h1_p + rA * 528 + j) = pack_e4m3x2(v0, v1);
                *reinterpret_cast<unsigned short*>(h1_p + rB * 528 + j) = pack_e4m3x2(v2, v3);
            }
    }
    __syncthreads();   // h1 complete; xs dead

    // ================= L1 (fp8): K=512 (KS=16); epilogue -> h2 e4m3 ===========
    {
        float C[64];
        #pragma unroll
        for (int i = 0; i < 64; i++) C[i] = 0.0f;
        gemm_fp8<16, 4, 4>(h1_b, 528, 0, wf4 + (GW1 >> 1), 16, nw * 2, lane, C);
        #pragma unroll
        for (int mt = 0; mt < 4; mt++)
            #pragma unroll
            for (int nt = 0; nt < 4; nt++) {
                const float* c = C + (mt * 4 + nt) * 4;
                const int j = (nw * 4 + nt) * 8 + t * 2;
                const int rA = mt * 16 + g, rB = rA + 8;
                const float v0 = fmaxf(fmaf(c[0], cs[1024 + j],     cs[1280 + j]),     0.0f);
                const float v1 = fmaxf(fmaf(c[1], cs[1024 + j + 1], cs[1280 + j + 1]), 0.0f);
                const float v2 = fmaxf(fmaf(c[2], cs[1024 + j],     cs[1280 + j]),     0.0f);
                const float v3 = fmaxf(fmaf(c[3], cs[1024 + j + 1], cs[1280 + j + 1]), 0.0f);
                *reinterpret_cast<unsigned short*>(xh_p + rA * 272 + j) = pack_e4m3x2(v0, v1);
                *reinterpret_cast<unsigned short*>(xh_p + rB * 272 + j) = pack_e4m3x2(v2, v3);
            }
    }
    __syncthreads();   // h2 complete; h1 dead

    // ================= Heads (fp8): K=256 (KS=8), NT=2 -> a3 bf16 =============
    {
        float C[32];
        #pragma unroll
        for (int i = 0; i < 32; i++) C[i] = 0.0f;
        gemm_fp8<8, 2, 4>(xh_b, 272, 0, wf4 + (GWH >> 1), 8, nw, lane, C);
        #pragma unroll
        for (int mt = 0; mt < 4; mt++)
            #pragma unroll
            for (int nt = 0; nt < 2; nt++) {
                const float* c = C + (mt * 2 + nt) * 4;
                const int j = (nw * 2 + nt) * 8 + t * 2;
                const int rA = mt * 16 + g, rB = rA + 8;
                const float v0 = fmaxf(c[0] + cs[1536 + j],     0.0f);
                const float v1 = fmaxf(c[1] + cs[1536 + j + 1], 0.0f);
                const float v2 = fmaxf(c[2] + cs[1536 + j],     0.0f);
                const float v3 = fmaxf(c[3] + cs[1536 + j + 1], 0.0f);
                a3[rA * 68 + (j >> 1)] = pack_bf16x2(v0, v1);
                a3[rB * 68 + (j >> 1)] = pack_bf16x2(v2, v3);
            }
    }
    __syncthreads();   // a3 complete; h2 dead

    // ================= Final (bf16): blockdiag -> logits (direct stores) ======
    {
        float C[64];
        #pragma unroll
        for (int i = 0; i < 64; i++) C[i] = 0.0f;
        const int ntb = nw * 4;                       // global nt 0..31
        const int kpb = (ntb >= 16) ? 32 : 0;         // doctor uses a3 u32 32..63
        gemm_bf16<4, 4, 4>(h1_b, 68, kpb, wf4 + (GWF >> 1), 16, ntb >> 1, lane, C);

        const int head = (ntb >= 16) ? 1 : 0;
        const int* sm  = head ? sds : sns;
        float* ob = out + (head ? (size_t)B_TOTAL * 128 : 0) + (size_t)r0 * 128;

        #pragma unroll
        for (int mt = 0; mt < 4; mt++)
            #pragma unroll
            for (int nt = 0; nt < 4; nt++) {
                const float* c = C + (mt * 4 + nt) * 4;
                const int jg  = (ntb + nt) * 8 + t * 2;
                const int col = jg & 127;
                const int rA = mt * 16 + g, rB = rA + 8;
                const int smA = sm[rA], smB = sm[rB];
                const float bb0 = cs[1664 + jg], bb1 = cs[1664 + jg + 1];
                float2 vA, vB;
                vA.x = (col     <= smA) ? (c[0] + bb0) : NEGV;
                vA.y = (col + 1 <= smA) ? (c[1] + bb1) : NEGV;
                vB.x = (col     <= smB) ? (c[2] + bb0) : NEGV;
                vB.y = (col + 1 <= smB) ? (c[3] + bb1) : NEGV;
                *reinterpret_cast<float2*>(ob + (size_t)rA * 128 + col) = vA;
                *reinterpret_cast<float2*>(ob + (size_t)rB * 128 + col) = vB;
            }
    }
}

extern "C" void kernel_launch(void* const* d_in, const int* in_sizes, int n_in,
                              void* d_out, int out_size)
{
    const float* x   = (const float*)d_in[0];
    const float* W0  = (const float*)d_in[1];
    const float* b0  = (const float*)d_in[2];
    const float* g0  = (const float*)d_in[3];
    const float* be0 = (const float*)d_in[4];
    const float* rm0 = (const float*)d_in[5];
    const float* rv0 = (const float*)d_in[6];
    const float* W1  = (const float*)d_in[7];
    const float* b1  = (const float*)d_in[8];
    const float* g1  = (const float*)d_in[9];
    const float* be1 = (const float*)d_in[10];
    const float* rm1 = (const float*)d_in[11];
    const float* rv1 = (const float*)d_in[12];
    const float* nW1 = (const float*)d_in[13];
    const float* nb1 = (const float*)d_in[14];
    const float* nW2 = (const float*)d_in[15];
    const float* nb2 = (const float*)d_in[16];
    const float* dW1 = (const float*)d_in[17];
    const float* db1 = (const float*)d_in[18];
    const float* dW2 = (const float*)d_in[19];
    const float* db2 = (const float*)d_in[20];

    cudaFuncSetAttribute(hosp_hyb_kernel,
                         cudaFuncAttributeMaxDynamicSharedMemorySize, SMEM_BYTES);

    hosp_prepack<<<128, 256>>>(W0, W1, nW1, dW1, nW2, dW2);
    hosp_hyb_kernel<<<B_TOTAL / 64, 256, SMEM_BYTES>>>(
        x, b0, g0, be0, rm0, rv0, b1, g1, be1, rm1, rv1,
        nb1, nb2, db1, db2, (float*)d_out);
}

// round 15
// speedup vs baseline: 1.1643x; 1.1643x over previous
#include <cuda_runtime.h>
#include <cuda_bf16.h>
#include <cstdint>

// ============================================================================
// HospitalStaffingModel via warp-level bf16 mma.sync (m16n8k16) on sm_103.
// Round 15: R11 config (64 rows/CTA, 256 thr, 8 N-warps, MT=4, NT=4, 2 CTA/SM,
// pair-interleaved LDG.128 B images, 4-deep B ring, JIT A pipeline) with the
// k-loop PF-blocked instead of fully unrolled -> ~8x smaller SASS for the
// long-K phases to relieve I-cache pressure. Math byte-identical to R11.
// ============================================================================

typedef unsigned long long ull;
#define B_TOTAL 131072
#define EPSV    1e-5f
#define NEGV    -1e9f

// ---- prepacked weight fragment buffer (ull entries, pair-interleaved) -------
#define GW0 0u        // W0: 4 ks x 32 np  -> 8192 ull
#define GW1 8192u     // W1: 32 ks x 16 np -> 32768
#define GWH 40960u    // [nW1|dW1]: 16 ks x 8 np -> 8192
#define GWF 49152u    // blockdiag(nW2,dW2): 4 ks x 16 np -> 4096
#define GTOT 53248u

__device__ __align__(1024) ull g_wfrag[GTOT];

// ---- SMEM layout (byte offsets) ---------------------------------------------
#define SO_CS    0        // 1920 f32 consts (7680 B)
#define SO_SN    7680     // 64 int
#define SO_SD    7936     // 64 int
#define SO_XH    8192     // region A: xs [64][36] u32 (L0) / h2 [64][132] u32
#define SO_H1    41984    // h1 bf16x2 [64][260] u32; a3 [64][68] overlays after L1
#define SMEM_BYTES 108544

// ---- helpers -----------------------------------------------------------------
__device__ __forceinline__ uint32_t smem_u32(const void* p) {
    uint32_t a;
    asm("{ .reg .u64 t; cvta.to.shared.u64 t, %1; cvt.u32.u64 %0, t; }" : "=r"(a) : "l"(p));
    return a;
}
__device__ __forceinline__ uint32_t pack_bf16x2(float lo, float hi) {
    uint32_t r;
    asm("cvt.rn.bf16x2.f32 %0, %1, %2;" : "=r"(r) : "f"(hi), "f"(lo));
    return r;
}
__device__ __forceinline__ void mma16816(float* c, const uint32_t* a, uint32_t b0, uint32_t b1) {
    asm volatile(
        "mma.sync.aligned.m16n8k16.row.col.f32.bf16.bf16.f32 "
        "{%0,%1,%2,%3}, {%4,%5,%6,%7}, {%8,%9}, {%0,%1,%2,%3};"
        : "+f"(c[0]), "+f"(c[1]), "+f"(c[2]), "+f"(c[3])
        : "r"(a[0]), "r"(a[1]), "r"(a[2]), "r"(a[3]), "r"(b0), "r"(b1));
}
__device__ __forceinline__ void ldsm_x4(uint32_t* r, uint32_t saddr) {
    asm volatile("ldmatrix.sync.aligned.m8n8.x4.shared.b16 {%0,%1,%2,%3}, [%4];"
                 : "=r"(r[0]), "=r"(r[1]), "=r"(r[2]), "=r"(r[3]) : "r"(saddr));
}

// Register-tiled block: C[MT][NT][4] += A[rows 0..16*MT) x Wfrag, K = KS*16.
// PF-blocked k-loop: outer loop steps PF, inner ki statically unrolled so the
// B-ring slot indices are compile-time. KS must be a multiple of PF.
// B via LDG.128 pair fetches (PF-1 prefetch distance); A via JIT ldsm pipeline.
template<int KS, int NT, int MT>
__device__ __forceinline__ void gemm_block(
    uint32_t act_saddr, int SA, int kpb,
    const uint4* __restrict__ wf, int NPW, int npb,
    int lane, float* C)
{
    constexpr int NP = NT / 2;
    constexpr int PF = (KS < 4) ? KS : 4;
    static_assert(KS % PF == 0, "KS must be a multiple of PF");
    const int quad  = lane >> 3;
    const int lrow  = (quad & 1) * 8 + (lane & 7);
    const int khalf = quad >> 1;
    const uint4* __restrict__ wfl = wf + (size_t)npb * 32 + lane;

    uint32_t abase[MT];
    #pragma unroll
    for (int mt = 0; mt < MT; mt++)
        abase[mt] = act_saddr + (uint32_t)(((mt * 16 + lrow) * SA + kpb + khalf * 4) * 4);

    uint4 b[PF][NP];
    #pragma unroll
    for (int s = 0; s < PF - 1; s++)
        #pragma unroll
        for (int np = 0; np < NP; np++)
            b[s][np] = wfl[((size_t)s * NPW + np) * 32];

    uint32_t a[2][4];
    ldsm_x4(a[0], abase[0]);                     // ks=0, mt=0

    #pragma unroll 1
    for (int kb = 0; kb < KS; kb += PF) {
        #pragma unroll
        for (int ki = 0; ki < PF; ki++) {
            const int ks = kb + ki;
            // prefetch B for ks+PF-1 into static ring slot (ki+PF-1)%PF
            if (ks + PF - 1 < KS) {
                #pragma unroll
                for (int np = 0; np < NP; np++)
                    b[(ki + PF - 1) % PF][np] = wfl[((size_t)(ks + PF - 1) * NPW + np) * 32];
            }
            #pragma unroll
            for (int mt = 0; mt < MT; mt++) {
                const int cur = mt & 1;          // MT even -> ks-independent parity
                if (mt + 1 < MT)
                    ldsm_x4(a[cur ^ 1], abase[mt + 1] + ks * 32);
                else if (ks + 1 < KS)
                    ldsm_x4(a[cur ^ 1], abase[0] + (ks + 1) * 32);
                const uint4* bb = b[ki];
                #pragma unroll
                for (int np = 0; np < NP; np++) {
                    mma16816(C + (mt * NT + np * 2) * 4,     a[cur], bb[np].x, bb[np].y);
                    mma16816(C + (mt * NT + np * 2 + 1) * 4, a[cur], bb[np].z, bb[np].w);
                }
            }
        }
    }
}

// ============================================================================
// Prepack: same fragment values as validated rounds, pair-interleaved layout.
// ============================================================================
__global__ void hosp_prepack(const float* __restrict__ W0, const float* __restrict__ W1,
                             const float* __restrict__ nW1, const float* __restrict__ dW1,
                             const float* __restrict__ nW2, const float* __restrict__ dW2)
{
    const int idx = blockIdx.x * 256 + threadIdx.x;
    if (idx >= (int)GTOT) return;
    const int lane = idx & 31;
    const int tg = lane & 3, gg = lane >> 2;
    float f0, f1, f2, f3;
    size_t dst;

    if (idx < 8192) {                       // W0 [64K x 512N], NPW=32
        const int gidx = idx >> 5;
        const int ks = gidx >> 6, nt = gidx & 63;
        const int k0 = ks * 16 + tg * 2, n = nt * 8 + gg;
        f0 = W0[(k0    ) * 512 + n]; f1 = W0[(k0 + 1) * 512 + n];
        f2 = W0[(k0 + 8) * 512 + n]; f3 = W0[(k0 + 9) * 512 + n];
        dst = GW0 + ((size_t)(ks * 32 + (nt >> 1)) * 32 + lane) * 2 + (nt & 1);
    } else if (idx < 40960) {               // W1 [512K x 256N], NPW=16
        const int gidx = (idx - 8192) >> 5;
        const int ks = gidx >> 5, nt = gidx & 31;
        const int k0 = ks * 16 + tg * 2, n = nt * 8 + gg;
        f0 = W1[(size_t)(k0    ) * 256 + n]; f1 = W1[(size_t)(k0 + 1) * 256 + n];
        f2 = W1[(size_t)(k0 + 8) * 256 + n]; f3 = W1[(size_t)(k0 + 9) * 256 + n];
        dst = GW1 + ((size_t)(ks * 16 + (nt >> 1)) * 32 + lane) * 2 + (nt & 1);
    } else if (idx < 49152) {               // [nW1|dW1] [256K x 128N], NPW=8
        const int gidx = (idx - 40960) >> 5;
        const int ks = gidx >> 4, nt = gidx & 15;
        const int k0 = ks * 16 + tg * 2, n = nt * 8 + gg;
        const float* W = (n < 64) ? nW1 : dW1;
        const int nn = n & 63;
        f0 = W[(k0    ) * 64 + nn]; f1 = W[(k0 + 1) * 64 + nn];
        f2 = W[(k0 + 8) * 64 + nn]; f3 = W[(k0 + 9) * 64 + nn];
        dst = GWH + ((size_t)(ks * 8 + (nt >> 1)) * 32 + lane) * 2 + (nt & 1);
    } else {                                // blockdiag(nW2,dW2) [64K x 256N], NPW=16
        const int gidx = (idx - 49152) >> 5;
        const int ks = gidx >> 5, nt = gidx & 31;
        const int k0 = ks * 16 + tg * 2;
        const float* W = (nt < 16) ? nW2 : dW2;
        const int n = ((nt & 15) * 8 + gg);
        f0 = W[(k0    ) * 128 + n]; f1 = W[(k0 + 1) * 128 + n];
        f2 = W[(k0 + 8) * 128 + n]; f3 = W[(k0 + 9) * 128 + n];
        dst = GWF + ((size_t)(ks * 16 + (nt >> 1)) * 32 + lane) * 2 + (nt & 1);
    }
    const uint32_t r0 = pack_bf16x2(f0, f1);
    const uint32_t r1 = pack_bf16x2(f2, f3);
    g_wfrag[dst] = (ull)r0 | ((ull)r1 << 32);
}

// ============================================================================
// Main kernel: 64 rows/CTA, 256 threads (8 N-warps, MT=4, NT=4). 2 CTAs/SM.
// ============================================================================
__global__ __launch_bounds__(256, 2)
void hosp_hmma_kernel(
    const float* __restrict__ x,
    const float* __restrict__ b0,  const float* __restrict__ g0,
    const float* __restrict__ be0, const float* __restrict__ rm0, const float* __restrict__ rv0,
    const float* __restrict__ b1,  const float* __restrict__ g1,
    const float* __restrict__ be1, const float* __restrict__ rm1, const float* __restrict__ rv1,
    const float* __restrict__ nb1, const float* __restrict__ nb2,
    const float* __restrict__ db1, const float* __restrict__ db2,
    float* __restrict__ out)
{
    extern __shared__ unsigned char smem[];
    float*    cs  = reinterpret_cast<float*>(smem + SO_CS);
    int*      sns = reinterpret_cast<int*>(smem + SO_SN);
    int*      sds = reinterpret_cast<int*>(smem + SO_SD);
    uint32_t* xs  = reinterpret_cast<uint32_t*>(smem + SO_XH);   // L0 only
    uint32_t* h2  = reinterpret_cast<uint32_t*>(smem + SO_XH);   // after L0
    uint32_t* h1  = reinterpret_cast<uint32_t*>(smem + SO_H1);
    uint32_t* a3  = reinterpret_cast<uint32_t*>(smem + SO_H1);   // after L1

    const uint32_t xh_b = smem_u32(smem + SO_XH);
    const uint32_t h1_b = smem_u32(smem + SO_H1);
    const uint4* wf4 = reinterpret_cast<const uint4*>(g_wfrag);

    const int tid  = threadIdx.x;
    const int lane = tid & 31;
    const int nw   = tid >> 5;         // N-warp (0..7)
    const int g    = lane >> 2, t = lane & 3;
    const int r0   = blockIdx.x * 64;

    // ---- fold BN consts + biases --------------------------------------------
    for (int i = tid; i < 512; i += 256) {
        const float s = g0[i] * rsqrtf(rv0[i] + EPSV);
        cs[i] = s; cs[512 + i] = (b0[i] - rm0[i]) * s + be0[i];
    }
    {
        const int i = tid;
        const float s = g1[i] * rsqrtf(rv1[i] + EPSV);
        cs[1024 + i] = s; cs[1280 + i] = (b1[i] - rm1[i]) * s + be1[i];
    }
    if (tid < 64) { cs[1536 + tid] = nb1[tid]; cs[1600 + tid] = db1[tid]; }
    if (tid < 128) { cs[1664 + tid] = nb2[tid]; cs[1792 + tid] = db2[tid]; }

    // ---- x tile: fp32 -> bf16x2, [64][36] + mask thresholds ------------------
    {
        const float2* x2 = reinterpret_cast<const float2*>(x + (size_t)r0 * 64);
        for (int i = tid; i < 2048; i += 256) {
            const int row = i >> 5, kp = i & 31;
            const float2 v = x2[row * 32 + kp];
            xs[row * 36 + kp] = pack_bf16x2(v.x, v.y);
        }
        if (tid < 64)       sns[tid] = (int)x[(size_t)(r0 + tid) * 64 + 60];
        else if (tid < 128) sds[tid - 64] = (int)x[(size_t)(r0 + tid - 64) * 64 + 61];
    }
    __syncthreads();

    // ================= L0: two N-halves of 4 n-tiles each =====================
    #pragma unroll 1
    for (int half = 0; half < 2; half++) {
        float C[64];
        #pragma unroll
        for (int i = 0; i < 64; i++) C[i] = 0.0f;
        const int ntb = nw * 8 + half * 4;
        gemm_block<4, 4, 4>(xh_b, 36, 0, wf4 + (GW0 >> 1), 32, ntb >> 1, lane, C);
        #pragma unroll
        for (int mt = 0; mt < 4; mt++)
            #pragma unroll
            for (int nt = 0; nt < 4; nt++) {
                const float* c = C + (mt * 4 + nt) * 4;
                const int j = (ntb + nt) * 8 + t * 2;
                const int rA = mt * 16 + g, rB = rA + 8;
                const float v0 = fmaxf(fmaf(c[0], cs[j],     cs[512 + j]),     0.0f);
                const float v1 = fmaxf(fmaf(c[1], cs[j + 1], cs[512 + j + 1]), 0.0f);
                const float v2 = fmaxf(fmaf(c[2], cs[j],     cs[512 + j]),     0.0f);
                const float v3 = fmaxf(fmaf(c[3], cs[j + 1], cs[512 + j + 1]), 0.0f);
                h1[rA * 260 + (j >> 1)] = pack_bf16x2(v0, v1);
                h1[rB * 260 + (j >> 1)] = pack_bf16x2(v2, v3);
            }
    }
    __syncthreads();   // h1 complete; xs dead

    // ================= L1: K=512 (KS=32, PF-blocked loop) ======================
    {
        float C[64];
        #pragma unroll
        for (int i = 0; i < 64; i++) C[i] = 0.0f;
        gemm_block<32, 4, 4>(h1_b, 260, 0, wf4 + (GW1 >> 1), 16, nw * 2, lane, C);
        #pragma unroll
        for (int mt = 0; mt < 4; mt++)
            #pragma unroll
            for (int nt = 0; nt < 4; nt++) {
                const float* c = C + (mt * 4 + nt) * 4;
                const int j = (nw * 4 + nt) * 8 + t * 2;
                const int rA = mt * 16 + g, rB = rA + 8;
                const float v0 = fmaxf(fmaf(c[0], cs[1024 + j],     cs[1280 + j]),     0.0f);
                const float v1 = fmaxf(fmaf(c[1], cs[1024 + j + 1], cs[1280 + j + 1]), 0.0f);
                const float v2 = fmaxf(fmaf(c[2], cs[1024 + j],     cs[1280 + j]),     0.0f);
                const float v3 = fmaxf(fmaf(c[3], cs[1024 + j + 1], cs[1280 + j + 1]), 0.0f);
                h2[rA * 132 + (j >> 1)] = pack_bf16x2(v0, v1);
                h2[rB * 132 + (j >> 1)] = pack_bf16x2(v2, v3);
            }
    }
    __syncthreads();   // h2 complete; h1 dead

    // ================= Heads: h2 @ [nW1|dW1] -> a3 (KS=16, blocked) ===========
    {
        float C[32];
        #pragma unroll
        for (int i = 0; i < 32; i++) C[i] = 0.0f;
        gemm_block<16, 2, 4>(xh_b, 132, 0, wf4 + (GWH >> 1), 8, nw, lane, C);
        #pragma unroll
        for (int mt = 0; mt < 4; mt++)
            #pragma unroll
            for (int nt = 0; nt < 2; nt++) {
                const float* c = C + (mt * 2 + nt) * 4;
                const int j = (nw * 2 + nt) * 8 + t * 2;
                const int rA = mt * 16 + g, rB = rA + 8;
                const float v0 = fmaxf(c[0] + cs[1536 + j],     0.0f);
                const float v1 = fmaxf(c[1] + cs[1536 + j + 1], 0.0f);
                const float v2 = fmaxf(c[2] + cs[1536 + j],     0.0f);
                const float v3 = fmaxf(c[3] + cs[1536 + j + 1], 0.0f);
                a3[rA * 68 + (j >> 1)] = pack_bf16x2(v0, v1);
                a3[rB * 68 + (j >> 1)] = pack_bf16x2(v2, v3);
            }
    }
    __syncthreads();   // a3 complete; h2 dead

    // ================= Final: a3 @ blockdiag -> logits (direct stores) ========
    {
        float C[64];
        #pragma unroll
        for (int i = 0; i < 64; i++) C[i] = 0.0f;
        const int ntb = nw * 4;                       // global nt 0..31
        const int kpb = (ntb >= 16) ? 32 : 0;         // doctor uses a3 cols 64..127
        gemm_block<4, 4, 4>(h1_b, 68, kpb, wf4 + (GWF >> 1), 16, ntb >> 1, lane, C);

        const int head = (ntb >= 16) ? 1 : 0;
        const int* sm  = head ? sds : sns;
        float* ob = out + (head ? (size_t)B_TOTAL * 128 : 0) + (size_t)r0 * 128;

        #pragma unroll
        for (int mt = 0; mt < 4; mt++)
            #pragma unroll
            for (int nt = 0; nt < 4; nt++) {
                const float* c = C + (mt * 4 + nt) * 4;
                const int jg  = (ntb + nt) * 8 + t * 2;
                const int col = jg & 127;
                const int rA = mt * 16 + g, rB = rA + 8;
                const int smA = sm[rA], smB = sm[rB];
                const float bb0 = cs[1664 + jg], bb1 = cs[1664 + jg + 1];
                float2 vA, vB;
                vA.x = (col     <= smA) ? (c[0] + bb0) : NEGV;
                vA.y = (col + 1 <= smA) ? (c[1] + bb1) : NEGV;
                vB.x = (col     <= smB) ? (c[2] + bb0) : NEGV;
                vB.y = (col + 1 <= smB) ? (c[3] + bb1) : NEGV;
                *reinterpret_cast<float2*>(ob + (size_t)rA * 128 + col) = vA;
                *reinterpret_cast<float2*>(ob + (size_t)rB * 128 + col) = vB;
            }
    }
}

extern "C" void kernel_launch(void* const* d_in, const int* in_sizes, int n_in,
                              void* d_out, int out_size)
{
    const float* x   = (const float*)d_in[0];
    const float* W0  = (const float*)d_in[1];
    const float* b0  = (const float*)d_in[2];
    const float* g0  = (const float*)d_in[3];
    const float* be0 = (const float*)d_in[4];
    const float* rm0 = (const float*)d_in[5];
    const float* rv0 = (const float*)d_in[6];
    const float* W1  = (const float*)d_in[7];
    const float* b1  = (const float*)d_in[8];
    const float* g1  = (const float*)d_in[9];
    const float* be1 = (const float*)d_in[10];
    const float* rm1 = (const float*)d_in[11];
    const float* rv1 = (const float*)d_in[12];
    const float* nW1 = (const float*)d_in[13];
    const float* nb1 = (const float*)d_in[14];
    const float* nW2 = (const float*)d_in[15];
    const float* nb2 = (const float*)d_in[16];
    const float* dW1 = (const float*)d_in[17];
    const float* db1 = (const float*)d_in[18];
    const float* dW2 = (const float*)d_in[19];
    const float* db2 = (const float*)d_in[20];

    cudaFuncSetAttribute(hosp_hmma_kernel,
                         cudaFuncAttributeMaxDynamicSharedMemorySize, SMEM_BYTES);

    hosp_prepack<<<208, 256>>>(W0, W1, nW1, dW1, nW2, dW2);
    hosp_hmma_kernel<<<B_TOTAL / 64, 256, SMEM_BYTES>>>(
        x, b0, g0, be0, rm0, rv0, b1, g1, be1, rm1, rv1,
        nb1, nb2, db1, db2, (float*)d_out);
}

// round 17
// speedup vs baseline: 1.2172x; 1.0454x over previous
#include <cuda_runtime.h>
#include <cuda_bf16.h>
#include <cstdint>

// ============================================================================
// HospitalStaffingModel via warp-level bf16 mma.sync (m16n8k16) on sm_103.
// Round 17: R16 with the const-copy overrun fixed (copy exactly 480 uint4;
// R16 wrote 512 and clobbered the mask arrays). GEMM structure = R11 champion:
// 64 rows/CTA, 256 thr, 8 N-warps, MT=4, NT=4, 2 CTA/SM, pair-interleaved
// LDG.128 B images, 4-deep B ring, JIT A pipeline. BN folds precomputed in
// prepack; prologue is a bounded 7.7KB uint4 copy + float4 x-tile load.
// ============================================================================

typedef unsigned long long ull;
#define B_TOTAL 131072
#define EPSV    1e-5f
#define NEGV    -1e9f

// ---- prepacked weight fragment buffer (ull entries, pair-interleaved) -------
#define GW0 0u        // W0: 4 ks x 32 np  -> 8192 ull
#define GW1 8192u     // W1: 32 ks x 16 np -> 32768
#define GWH 40960u    // [nW1|dW1]: 16 ks x 8 np -> 8192
#define GWF 49152u    // blockdiag(nW2,dW2): 4 ks x 16 np -> 4096
#define GTOT 53248u
#define NCONST 1920   // folded consts (float) = 480 uint4

__device__ __align__(1024) ull   g_wfrag[GTOT];
__device__ __align__(16)   float g_consts[NCONST];

// ---- SMEM layout (byte offsets) ---------------------------------------------
#define SO_CS    0        // 1920 f32 consts (7680 B)
#define SO_SN    7680     // 64 int
#define SO_SD    7936     // 64 int
#define SO_XH    8192     // region A: xs [64][36] u32 (L0) / h2 [64][132] u32
#define SO_H1    41984    // h1 bf16x2 [64][260] u32; a3 [64][68] overlays after L1
#define SMEM_BYTES 108544

// ---- helpers -----------------------------------------------------------------
__device__ __forceinline__ uint32_t smem_u32(const void* p) {
    uint32_t a;
    asm("{ .reg .u64 t; cvta.to.shared.u64 t, %1; cvt.u32.u64 %0, t; }" : "=r"(a) : "l"(p));
    return a;
}
__device__ __forceinline__ uint32_t pack_bf16x2(float lo, float hi) {
    uint32_t r;
    asm("cvt.rn.bf16x2.f32 %0, %1, %2;" : "=r"(r) : "f"(hi), "f"(lo));
    return r;
}
__device__ __forceinline__ void mma16816(float* c, const uint32_t* a, uint32_t b0, uint32_t b1) {
    asm volatile(
        "mma.sync.aligned.m16n8k16.row.col.f32.bf16.bf16.f32 "
        "{%0,%1,%2,%3}, {%4,%5,%6,%7}, {%8,%9}, {%0,%1,%2,%3};"
        : "+f"(c[0]), "+f"(c[1]), "+f"(c[2]), "+f"(c[3])
        : "r"(a[0]), "r"(a[1]), "r"(a[2]), "r"(a[3]), "r"(b0), "r"(b1));
}
__device__ __forceinline__ void ldsm_x4(uint32_t* r, uint32_t saddr) {
    asm volatile("ldmatrix.sync.aligned.m8n8.x4.shared.b16 {%0,%1,%2,%3}, [%4];"
                 : "=r"(r[0]), "=r"(r[1]), "=r"(r[2]), "=r"(r[3]) : "r"(saddr));
}

// Register-tiled block (identical to R11): C[MT][NT][4] += A x Wfrag, K=KS*16.
// B via LDG.128 pair fetches, PF-deep register ring (PF=4); A via 2-buffer
// JIT ldmatrix pipeline.
template<int KS, int NT, int MT>
__device__ __forceinline__ void gemm_block(
    uint32_t act_saddr, int SA, int kpb,
    const uint4* __restrict__ wf, int NPW, int npb,
    int lane, float* C)
{
    constexpr int NP = NT / 2;
    constexpr int PF = (KS < 4) ? KS : 4;
    const int quad  = lane >> 3;
    const int lrow  = (quad & 1) * 8 + (lane & 7);
    const int khalf = quad >> 1;
    const uint4* __restrict__ wfl = wf + (size_t)npb * 32 + lane;

    uint32_t abase[MT];
    #pragma unroll
    for (int mt = 0; mt < MT; mt++)
        abase[mt] = act_saddr + (uint32_t)(((mt * 16 + lrow) * SA + kpb + khalf * 4) * 4);

    uint4 b[PF][NP];
    #pragma unroll
    for (int s = 0; s < PF - 1; s++)
        #pragma unroll
        for (int np = 0; np < NP; np++)
            b[s][np] = wfl[((size_t)s * NPW + np) * 32];

    uint32_t a[2][4];
    ldsm_x4(a[0], abase[0]);                     // ks=0, mt=0

    #pragma unroll
    for (int ks = 0; ks < KS; ks++) {
        if (ks + PF - 1 < KS) {
            #pragma unroll
            for (int np = 0; np < NP; np++)
                b[(ks + PF - 1) % PF][np] = wfl[((size_t)(ks + PF - 1) * NPW + np) * 32];
        }
        #pragma unroll
        for (int mt = 0; mt < MT; mt++) {
            const int cur = (ks * MT + mt) & 1;
            if (mt + 1 < MT)
                ldsm_x4(a[cur ^ 1], abase[mt + 1] + ks * 32);
            else if (ks + 1 < KS)
                ldsm_x4(a[cur ^ 1], abase[0] + (ks + 1) * 32);
            const uint4* bb = b[ks % PF];
            #pragma unroll
            for (int np = 0; np < NP; np++) {
                mma16816(C + (mt * NT + np * 2) * 4,     a[cur], bb[np].x, bb[np].y);
                mma16816(C + (mt * NT + np * 2 + 1) * 4, a[cur], bb[np].z, bb[np].w);
            }
        }
    }
}

// ============================================================================
// Prepack: weight fragment images (pair-interleaved) + folded BN consts.
// ============================================================================
__global__ void hosp_prepack(const float* __restrict__ W0, const float* __restrict__ W1,
                             const float* __restrict__ nW1, const float* __restrict__ dW1,
                             const float* __restrict__ nW2, const float* __restrict__ dW2,
                             const float* __restrict__ b0,  const float* __restrict__ g0,
                             const float* __restrict__ be0, const float* __restrict__ rm0,
                             const float* __restrict__ rv0,
                             const float* __restrict__ b1,  const float* __restrict__ g1,
                             const float* __restrict__ be1, const float* __restrict__ rm1,
                             const float* __restrict__ rv1,
                             const float* __restrict__ nb1, const float* __restrict__ nb2,
                             const float* __restrict__ db1, const float* __restrict__ db2)
{
    const int idx = blockIdx.x * 256 + threadIdx.x;

    if (idx >= (int)GTOT) {                      // folded consts
        const int c = idx - (int)GTOT;
        if (c < 512) {
            const float s = g0[c] * rsqrtf(rv0[c] + EPSV);
            g_consts[c] = s;
            g_consts[512 + c] = (b0[c] - rm0[c]) * s + be0[c];
        } else if (c < 768) {
            const int i = c - 512;
            const float s = g1[i] * rsqrtf(rv1[i] + EPSV);
            g_consts[1024 + i] = s;
            g_consts[1280 + i] = (b1[i] - rm1[i]) * s + be1[i];
        } else if (c < 832) {
            const int i = c - 768;
            g_consts[1536 + i] = nb1[i];
            g_consts[1600 + i] = db1[i];
        } else if (c < 960) {
            const int i = c - 832;
            g_consts[1664 + i] = nb2[i];
            g_consts[1792 + i] = db2[i];
        }
        return;
    }

    const int lane = idx & 31;
    const int tg = lane & 3, gg = lane >> 2;
    float f0, f1, f2, f3;
    size_t dst;

    if (idx < 8192) {                       // W0 [64K x 512N], NPW=32
        const int gidx = idx >> 5;
        const int ks = gidx >> 6, nt = gidx & 63;
        const int k0 = ks * 16 + tg * 2, n = nt * 8 + gg;
        f0 = W0[(k0    ) * 512 + n]; f1 = W0[(k0 + 1) * 512 + n];
        f2 = W0[(k0 + 8) * 512 + n]; f3 = W0[(k0 + 9) * 512 + n];
        dst = GW0 + ((size_t)(ks * 32 + (nt >> 1)) * 32 + lane) * 2 + (nt & 1);
    } else if (idx < 40960) {               // W1 [512K x 256N], NPW=16
        const int gidx = (idx - 8192) >> 5;
        const int ks = gidx >> 5, nt = gidx & 31;
        const int k0 = ks * 16 + tg * 2, n = nt * 8 + gg;
        f0 = W1[(size_t)(k0    ) * 256 + n]; f1 = W1[(size_t)(k0 + 1) * 256 + n];
        f2 = W1[(size_t)(k0 + 8) * 256 + n]; f3 = W1[(size_t)(k0 + 9) * 256 + n];
        dst = GW1 + ((size_t)(ks * 16 + (nt >> 1)) * 32 + lane) * 2 + (nt & 1);
    } else if (idx < 49152) {               // [nW1|dW1] [256K x 128N], NPW=8
        const int gidx = (idx - 40960) >> 5;
        const int ks = gidx >> 4, nt = gidx & 15;
        const int k0 = ks * 16 + tg * 2, n = nt * 8 + gg;
        const float* W = (n < 64) ? nW1 : dW1;
        const int nn = n & 63;
        f0 = W[(k0    ) * 64 + nn]; f1 = W[(k0 + 1) * 64 + nn];
        f2 = W[(k0 + 8) * 64 + nn]; f3 = W[(k0 + 9) * 64 + nn];
        dst = GWH + ((size_t)(ks * 8 + (nt >> 1)) * 32 + lane) * 2 + (nt & 1);
    } else {                                // blockdiag(nW2,dW2) [64K x 256N], NPW=16
        const int gidx = (idx - 49152) >> 5;
        const int ks = gidx >> 5, nt = gidx & 31;
        const int k0 = ks * 16 + tg * 2;
        const float* W = (nt < 16) ? nW2 : dW2;
        const int n = ((nt & 15) * 8 + gg);
        f0 = W[(k0    ) * 128 + n]; f1 = W[(k0 + 1) * 128 + n];
        f2 = W[(k0 + 8) * 128 + n]; f3 = W[(k0 + 9) * 128 + n];
        dst = GWF + ((size_t)(ks * 16 + (nt >> 1)) * 32 + lane) * 2 + (nt & 1);
    }
    const uint32_t r0 = pack_bf16x2(f0, f1);
    const uint32_t r1 = pack_bf16x2(f2, f3);
    g_wfrag[dst] = (ull)r0 | ((ull)r1 << 32);
}

// ============================================================================
// Main kernel: 64 rows/CTA, 256 threads (8 N-warps, MT=4, NT=4). 2 CTAs/SM.
// ============================================================================
__global__ __launch_bounds__(256, 2)
void hosp_hmma_kernel(const float* __restrict__ x, float* __restrict__ out)
{
    extern __shared__ unsigned char smem[];
    float*    cs  = reinterpret_cast<float*>(smem + SO_CS);
    int*      sns = reinterpret_cast<int*>(smem + SO_SN);
    int*      sds = reinterpret_cast<int*>(smem + SO_SD);
    uint32_t* xs  = reinterpret_cast<uint32_t*>(smem + SO_XH);   // L0 only
    uint32_t* h2  = reinterpret_cast<uint32_t*>(smem + SO_XH);   // after L0
    uint32_t* h1  = reinterpret_cast<uint32_t*>(smem + SO_H1);
    uint32_t* a3  = reinterpret_cast<uint32_t*>(smem + SO_H1);   // after L1

    const uint32_t xh_b = smem_u32(smem + SO_XH);
    const uint32_t h1_b = smem_u32(smem + SO_H1);
    const uint4* wf4 = reinterpret_cast<const uint4*>(g_wfrag);

    const int tid  = threadIdx.x;
    const int lane = tid & 31;
    const int nw   = tid >> 5;         // N-warp (0..7)
    const int g    = lane >> 2, t = lane & 3;
    const int r0   = blockIdx.x * 64;

    // ---- prologue: bounded const copy (480 uint4) + vectorized x tile --------
    {
        const uint4* gc = reinterpret_cast<const uint4*>(g_consts);
        uint4* cs4 = reinterpret_cast<uint4*>(cs);
        for (int i = tid; i < NCONST / 4; i += 256)    // exactly 480 uint4
            cs4[i] = gc[i];
    }
    {
        const float4* x4 = reinterpret_cast<const float4*>(x + (size_t)r0 * 64);
        #pragma unroll
        for (int i = 0; i < 4; i++) {
            const int e = tid + i * 256;              // 0..1023
            const int row = e >> 4, kq = e & 15;
            const float4 v = x4[row * 16 + kq];
            xs[row * 36 + kq * 2]     = pack_bf16x2(v.x, v.y);
            xs[row * 36 + kq * 2 + 1] = pack_bf16x2(v.z, v.w);
        }
        if (tid < 64)       sns[tid] = (int)x[(size_t)(r0 + tid) * 64 + 60];
        else if (tid < 128) sds[tid - 64] = (int)x[(size_t)(r0 + tid - 64) * 64 + 61];
    }
    __syncthreads();

    // ================= L0: two N-halves of 4 n-tiles each =====================
    #pragma unroll 1
    for (int half = 0; half < 2; half++) {
        float C[64];
        #pragma unroll
        for (int i = 0; i < 64; i++) C[i] = 0.0f;
        const int ntb = nw * 8 + half * 4;
        gemm_block<4, 4, 4>(xh_b, 36, 0, wf4 + (GW0 >> 1), 32, ntb >> 1, lane, C);
        #pragma unroll
        for (int mt = 0; mt < 4; mt++)
            #pragma unroll
            for (int nt = 0; nt < 4; nt++) {
                const float* c = C + (mt * 4 + nt) * 4;
                const int j = (ntb + nt) * 8 + t * 2;
                const int rA = mt * 16 + g, rB = rA + 8;
                const float v0 = fmaxf(fmaf(c[0], cs[j],     cs[512 + j]),     0.0f);
                const float v1 = fmaxf(fmaf(c[1], cs[j + 1], cs[512 + j + 1]), 0.0f);
                const float v2 = fmaxf(fmaf(c[2], cs[j],     cs[512 + j]),     0.0f);
                const float v3 = fmaxf(fmaf(c[3], cs[j + 1], cs[512 + j + 1]), 0.0f);
                h1[rA * 260 + (j >> 1)] = pack_bf16x2(v0, v1);
                h1[rB * 260 + (j >> 1)] = pack_bf16x2(v2, v3);
            }
    }
    __syncthreads();   // h1 complete; xs dead

    // ================= L1: K=512 in one pipelined sweep =======================
    {
        float C[64];
        #pragma unroll
        for (int i = 0; i < 64; i++) C[i] = 0.0f;
        gemm_block<32, 4, 4>(h1_b, 260, 0, wf4 + (GW1 >> 1), 16, nw * 2, lane, C);
        #pragma unroll
        for (int mt = 0; mt < 4; mt++)
            #pragma unroll
            for (int nt = 0; nt < 4; nt++) {
                const float* c = C + (mt * 4 + nt) * 4;
                const int j = (nw * 4 + nt) * 8 + t * 2;
                const int rA = mt * 16 + g, rB = rA + 8;
                const float v0 = fmaxf(fmaf(c[0], cs[1024 + j],     cs[1280 + j]),     0.0f);
                const float v1 = fmaxf(fmaf(c[1], cs[1024 + j + 1], cs[1280 + j + 1]), 0.0f);
                const float v2 = fmaxf(fmaf(c[2], cs[1024 + j],     cs[1280 + j]),     0.0f);
                const float v3 = fmaxf(fmaf(c[3], cs[1024 + j + 1], cs[1280 + j + 1]), 0.0f);
                h2[rA * 132 + (j >> 1)] = pack_bf16x2(v0, v1);
                h2[rB * 132 + (j >> 1)] = pack_bf16x2(v2, v3);
            }
    }
    __syncthreads();   // h2 complete; h1 dead

    // ================= Heads: h2 @ [nW1|dW1] -> a3 ============================
    {
        float C[32];
        #pragma unroll
        for (int i = 0; i < 32; i++) C[i] = 0.0f;
        gemm_block<16, 2, 4>(xh_b, 132, 0, wf4 + (GWH >> 1), 8, nw, lane, C);
        #pragma unroll
        for (int mt = 0; mt < 4; mt++)
            #pragma unroll
            for (int nt = 0; nt < 2; nt++) {
                const float* c = C + (mt * 2 + nt) * 4;
                const int j = (nw * 2 + nt) * 8 + t * 2;
                const int rA = mt * 16 + g, rB = rA + 8;
                const float v0 = fmaxf(c[0] + cs[1536 + j],     0.0f);
                const float v1 = fmaxf(c[1] + cs[1536 + j + 1], 0.0f);
                const float v2 = fmaxf(c[2] + cs[1536 + j],     0.0f);
                const float v3 = fmaxf(c[3] + cs[1536 + j + 1], 0.0f);
                a3[rA * 68 + (j >> 1)] = pack_bf16x2(v0, v1);
                a3[rB * 68 + (j >> 1)] = pack_bf16x2(v2, v3);
            }
    }
    __syncthreads();   // a3 complete; h2 dead

    // ================= Final: a3 @ blockdiag -> logits (direct stores) ========
    {
        float C[64];
        #pragma unroll
        for (int i = 0; i < 64; i++) C[i] = 0.0f;
        const int ntb = nw * 4;                       // global nt 0..31
        const int kpb = (ntb >= 16) ? 32 : 0;         // doctor uses a3 cols 64..127
        gemm_block<4, 4, 4>(h1_b, 68, kpb, wf4 + (GWF >> 1), 16, ntb >> 1, lane, C);

        const int head = (ntb >= 16) ? 1 : 0;
        const int* sm  = head ? sds : sns;
        float* ob = out + (head ? (size_t)B_TOTAL * 128 : 0) + (size_t)r0 * 128;

        #pragma unroll
        for (int mt = 0; mt < 4; mt++)
            #pragma unroll
            for (int nt = 0; nt < 4; nt++) {
                const float* c = C + (mt * 4 + nt) * 4;
                const int jg  = (ntb + nt) * 8 + t * 2;
                const int col = jg & 127;
                const int rA = mt * 16 + g, rB = rA + 8;
                const int smA = sm[rA], smB = sm[rB];
                const float bb0 = cs[1664 + jg], bb1 = cs[1664 + jg + 1];
                float2 vA, vB;
                vA.x = (col     <= smA) ? (c[0] + bb0) : NEGV;
                vA.y = (col + 1 <= smA) ? (c[1] + bb1) : NEGV;
                vB.x = (col     <= smB) ? (c[2] + bb0) : NEGV;
                vB.y = (col + 1 <= smB) ? (c[3] + bb1) : NEGV;
                *reinterpret_cast<float2*>(ob + (size_t)rA * 128 + col) = vA;
                *reinterpret_cast<float2*>(ob + (size_t)rB * 128 + col) = vB;
            }
    }
}

extern "C" void kernel_launch(void* const* d_in, const int* in_sizes, int n_in,
                              void* d_out, int out_size)
{
    const float* x   = (const float*)d_in[0];
    const float* W0  = (const float*)d_in[1];
    const float* b0  = (const float*)d_in[2];
    const float* g0  = (const float*)d_in[3];
    const float* be0 = (const float*)d_in[4];
    const float* rm0 = (const float*)d_in[5];
    const float* rv0 = (const float*)d_in[6];
    const float* W1  = (const float*)d_in[7];
    const float* b1  = (const float*)d_in[8];
    const float* g1  = (const float*)d_in[9];
    const float* be1 = (const float*)d_in[10];
    const float* rm1 = (const float*)d_in[11];
    const float* rv1 = (const float*)d_in[12];
    const float* nW1 = (const float*)d_in[13];
    const float* nb1 = (const float*)d_in[14];
    const float* nW2 = (const float*)d_in[15];
    const float* nb2 = (const float*)d_in[16];
    const float* dW1 = (const float*)d_in[17];
    const float* db1 = (const float*)d_in[18];
    const float* dW2 = (const float*)d_in[19];
    const float* db2 = (const float*)d_in[20];

    cudaFuncSetAttribute(hosp_hmma_kernel,
                         cudaFuncAttributeMaxDynamicSharedMemorySize, SMEM_BYTES);

    // GTOT weight-fragment entries + 960 const-fold threads (covers 1920 floats)
    hosp_prepack<<<212, 256>>>(W0, W1, nW1, dW1, nW2, dW2,
                               b0, g0, be0, rm0, rv0,
                               b1, g1, be1, rm1, rv1,
                               nb1, nb2, db1, db2);
    hosp_hmma_kernel<<<B_TOTAL / 64, 256, SMEM_BYTES>>>(x, (float*)d_out);
}